// round 4
// baseline (speedup 1.0000x reference)
#include <cuda_runtime.h>

#define N_NODES 50000
#define N_EDGES 200000
#define F_IN 100
#define HID 1024

#define NB_FOLD  (F_IN + 1)                        // 101 blocks
#define NB_E4    ((N_EDGES / 4 + 255) / 256)       // 196 blocks (4 edges/thread)
#define NB_NODE  ((N_NODES * 32 + 255) / 256)      // 6250 blocks, warp-per-node

// Scratch (no device allocation allowed). g_deg starts 0 and is reset to 0
// by node_kernel every run, so every graph replay sees a clean state.
__device__ float g_w[F_IN];
__device__ float g_c;
__device__ float g_deg[N_NODES];
__device__ float g_dinv[N_NODES];
__device__ float g_p[N_NODES];

// Per-block edge-dtype detect: int64-LE values < 50000 have all-zero odd
// 32-bit words. 128 random int32 endpoints all being zero: prob ~ 0.
__device__ __forceinline__ bool detect_is64(const int* __restrict__ ebuf) {
    __shared__ int nz;
    if (threadIdx.x == 0) nz = 0;
    __syncthreads();
    if (threadIdx.x < 128 && ebuf[2 * threadIdx.x + 1] != 0) nz = 1;
    __syncthreads();
    return nz == 0;
}

// Load 4 consecutive edge endpoints starting at logical position `pos`
// (pos % 4 == 0, pos+3 within the logical int array of that half).
__device__ __forceinline__ void load_edges4(const int* __restrict__ ebuf,
                                            long long pos, bool is64,
                                            int& a, int& b, int& c, int& d) {
    if (is64) {
        int4 v0 = ((const int4*)ebuf)[pos >> 1];
        int4 v1 = ((const int4*)ebuf)[(pos >> 1) + 1];
        a = v0.x; b = v0.z; c = v1.x; d = v1.z;
    } else {
        int4 v = ((const int4*)ebuf)[pos >> 2];
        a = v.x; b = v.y; c = v.z; d = v.w;
    }
}

// ---------------------------------------------------------------------------
// K1: blocks [0,101) fold w = W1 @ W_head (and c); blocks [101, 101+NB_E4)
// accumulate in-degrees, 4 edges/thread. Independent roles.
// ---------------------------------------------------------------------------
__global__ void setup_and_deg(const int* __restrict__ ebuf,
                              const float* __restrict__ W1,
                              const float* __restrict__ b1,
                              const float* __restrict__ Wh,
                              const float* __restrict__ bh) {
    int blk = blockIdx.x;
    int t = threadIdx.x;

    if (blk < NB_FOLD) {
        __shared__ float red[256];
        float acc = 0.f;
        if (blk < F_IN) {
            const float* row = W1 + (long long)blk * HID;
            for (int k = t; k < HID; k += 256) acc += row[k] * Wh[k];
        } else {
            for (int k = t; k < HID; k += 256) acc += b1[k] * Wh[k];
        }
        red[t] = acc;
        __syncthreads();
        for (int s = 128; s > 0; s >>= 1) {
            if (t < s) red[t] += red[t + s];
            __syncthreads();
        }
        if (t == 0) {
            if (blk < F_IN) g_w[blk] = red[0];
            else            g_c     = red[0] + bh[0];
        }
        return;
    }

    bool is64 = detect_is64(ebuf);
    int e = ((blk - NB_FOLD) * 256 + t) * 4;
    if (e >= N_EDGES) return;   // N_EDGES % 4 == 0: no partial batches
    int d0, d1, d2, d3;
    load_edges4(ebuf, (long long)N_EDGES + e, is64, d0, d1, d2, d3);
    if ((unsigned)d0 < N_NODES) atomicAdd(&g_deg[d0], 1.0f);
    if ((unsigned)d1 < N_NODES) atomicAdd(&g_deg[d1], 1.0f);
    if ((unsigned)d2 < N_NODES) atomicAdd(&g_deg[d2], 1.0f);
    if ((unsigned)d3 < N_NODES) atomicAdd(&g_deg[d3], 1.0f);
}

// ---------------------------------------------------------------------------
// K2: warp-per-node: s = x[n]·w (float4 loads), then finalize that node:
// dinv, p, out = c + s*dinv^2; reset deg to 0 for the next replay.
// ---------------------------------------------------------------------------
__global__ void node_kernel(const float* __restrict__ x, float* __restrict__ out) {
    __shared__ __align__(16) float sw[F_IN + 4];   // pad so float4 reads stay in-bounds
    int t = threadIdx.x;
    for (int i = t; i < F_IN + 4; i += blockDim.x) sw[i] = (i < F_IN) ? g_w[i] : 0.f;
    __syncthreads();

    int node = (blockIdx.x * 256 + t) >> 5;
    int lane = t & 31;
    if (node >= N_NODES) return;

    float acc = 0.f;
    if (lane < 25) {   // 25 float4 = 100 floats; row base is 16B-aligned (400B stride)
        float4 xv = ((const float4*)(x + (long long)node * F_IN))[lane];
        float4 wv = ((const float4*)sw)[lane];
        acc = xv.x * wv.x + xv.y * wv.y + xv.z * wv.z + xv.w * wv.w;
    }

    #pragma unroll
    for (int o = 16; o > 0; o >>= 1)
        acc += __shfl_down_sync(0xffffffffu, acc, o);

    if (lane == 0) {
        float deg = g_deg[node] + 1.0f;   // +1 self loop (deg buffer starts at 0)
        g_deg[node] = 0.0f;               // restore for next graph replay
        float d = rsqrtf(deg);
        g_dinv[node] = d;
        g_p[node]    = acc * d;
        out[node]    = g_c + acc * d * d;
    }
}

// ---------------------------------------------------------------------------
// K3: edge scatter, 4 edges/thread: out[dst] += p[src] * dinv[dst].
// All 8 gathers issued before any atomic -> MLP 8.
// ---------------------------------------------------------------------------
__global__ void edge_scatter(const int* __restrict__ ebuf,
                             float* __restrict__ out) {
    bool is64 = detect_is64(ebuf);
    int e = (blockIdx.x * 256 + threadIdx.x) * 4;
    if (e >= N_EDGES) return;

    int s0, s1, s2, s3, d0, d1, d2, d3;
    load_edges4(ebuf, e, is64, s0, s1, s2, s3);
    load_edges4(ebuf, (long long)N_EDGES + e, is64, d0, d1, d2, d3);

    bool v0 = (unsigned)s0 < N_NODES && (unsigned)d0 < N_NODES;
    bool v1 = (unsigned)s1 < N_NODES && (unsigned)d1 < N_NODES;
    bool v2 = (unsigned)s2 < N_NODES && (unsigned)d2 < N_NODES;
    bool v3 = (unsigned)s3 < N_NODES && (unsigned)d3 < N_NODES;

    float p0 = v0 ? g_p[s0] : 0.f,  q0 = v0 ? g_dinv[d0] : 0.f;
    float p1 = v1 ? g_p[s1] : 0.f,  q1 = v1 ? g_dinv[d1] : 0.f;
    float p2 = v2 ? g_p[s2] : 0.f,  q2 = v2 ? g_dinv[d2] : 0.f;
    float p3 = v3 ? g_p[s3] : 0.f,  q3 = v3 ? g_dinv[d3] : 0.f;

    if (v0) atomicAdd(&out[d0], p0 * q0);
    if (v1) atomicAdd(&out[d1], p1 * q1);
    if (v2) atomicAdd(&out[d2], p2 * q2);
    if (v3) atomicAdd(&out[d3], p3 * q3);
}

extern "C" void kernel_launch(void* const* d_in, const int* in_sizes, int n_in,
                              void* d_out, int out_size) {
    const float* state = (const float*)d_in[0];  // [N, 100, 1] f32
    const int*   ebuf  = (const int*)  d_in[1];  // [2, 200000] int32/int64 layout
    const float* W1    = (const float*)d_in[2];  // [100, 1024]
    const float* b1    = (const float*)d_in[3];  // [1024]
    const float* Wh    = (const float*)d_in[4];  // [1024, 1]
    const float* bh    = (const float*)d_in[5];  // [1]
    float* out = (float*)d_out;                  // [N, 1]

    setup_and_deg<<<NB_FOLD + NB_E4, 256>>>(ebuf, W1, b1, Wh, bh);
    node_kernel  <<<NB_NODE, 256>>>(state, out);
    edge_scatter <<<NB_E4, 256>>>(ebuf, out);
}

// round 5
// speedup vs baseline: 3.0812x; 3.0812x over previous
#include <cuda_runtime.h>

#define N_NODES 50000
#define N_EDGES 200000
#define F_IN 100
#define HID 1024

#define NB_DEG   ((N_NODES + 255) / 256)          // 196 blocks, per-node work
#define NB_NODE  ((N_NODES * 32 + 255) / 256)     // 6250 blocks, warp-per-node
#define NB_EDGE  ((N_EDGES + 255) / 256)          // 782 blocks, thread-per-edge
#define NB_E2    ((N_EDGES / 2 + 255) / 256)      // 391 blocks, 2 edges/thread

// Scratch (no device allocation allowed)
__device__ float g_w[F_IN];
__device__ float g_c;
__device__ float g_deg[N_NODES];
__device__ float g_dinv[N_NODES];
__device__ float g_s[N_NODES];   // s[n] = x[n]·w
__device__ float g_p[N_NODES];   // p[n] = s[n] * dinv[n]
__device__ int   g_is64;

// ---------------------------------------------------------------------------
// K1 (fused setup): block 0 = dtype detect, blocks 1..101 = head fold,
// blocks 102.. = degree init to 1.0 (self loop). All independent.
// ---------------------------------------------------------------------------
__global__ void setup_kernel(const int* __restrict__ ebuf,
                             const float* __restrict__ W1,
                             const float* __restrict__ b1,
                             const float* __restrict__ Wh,
                             const float* __restrict__ bh) {
    int blk = blockIdx.x;
    int t = threadIdx.x;

    if (blk == 0) {
        // int64-little-endian edge values < 50000 => every odd 32-bit word is 0.
        __shared__ int any_nonzero;
        if (t == 0) any_nonzero = 0;
        __syncthreads();
        for (int i = t; i < 1024; i += blockDim.x)
            if (ebuf[2 * i + 1] != 0) any_nonzero = 1;
        __syncthreads();
        if (t == 0) g_is64 = any_nonzero ? 0 : 1;
        return;
    }
    if (blk <= F_IN + 1) {
        int b = blk - 1;  // 0..100
        __shared__ float red[256];
        float acc = 0.f;
        if (b < F_IN) {
            const float* row = W1 + (long long)b * HID;
            for (int k = t; k < HID; k += 256) acc += row[k] * Wh[k];
        } else {
            for (int k = t; k < HID; k += 256) acc += b1[k] * Wh[k];
        }
        red[t] = acc;
        __syncthreads();
        for (int s = 128; s > 0; s >>= 1) {
            if (t < s) red[t] += red[t + s];
            __syncthreads();
        }
        if (t == 0) {
            if (b < F_IN) g_w[b] = red[0];
            else          g_c   = red[0] + bh[0];
        }
        return;
    }
    // degree init
    int i = (blk - (F_IN + 2)) * 256 + t;
    if (i < N_NODES) g_deg[i] = 1.0f;
}

__device__ __forceinline__ int load_edge(const int* ebuf, long long pos) {
    if (g_is64) return ((const int2*)ebuf)[pos].x;   // coalesced 8B load, lo word
    return ebuf[pos];
}

// ---------------------------------------------------------------------------
// K2 (fused): blocks [0, NB_EDGE) = degree atomics over edges (launched FIRST
// so they finish under cover of the long x-stream); blocks [NB_EDGE, ...) =
// warp-per-node dot product s[n] = x[n]·w.
// ---------------------------------------------------------------------------
__global__ void dot_and_deg_kernel(const float* __restrict__ x,
                                   const int* __restrict__ ebuf) {
    int blk = blockIdx.x;
    int t = threadIdx.x;

    if (blk < NB_EDGE) {
        int e = blk * 256 + t;
        if (e < N_EDGES) {
            int dst = load_edge(ebuf, (long long)N_EDGES + e);
            if (dst >= 0 && dst < N_NODES)
                atomicAdd(&g_deg[dst], 1.0f);
        }
        return;
    }

    __shared__ float sw[F_IN];
    for (int i = t; i < F_IN; i += blockDim.x) sw[i] = g_w[i];
    __syncthreads();

    int node = ((blk - NB_EDGE) * 256 + t) >> 5;
    int lane = t & 31;
    if (node >= N_NODES) return;

    const float* xr = x + (long long)node * F_IN;
    float acc = xr[lane]      * sw[lane]
              + xr[lane + 32] * sw[lane + 32]
              + xr[lane + 64] * sw[lane + 64];
    if (lane < 4) acc += xr[lane + 96] * sw[lane + 96];

    #pragma unroll
    for (int o = 16; o > 0; o >>= 1)
        acc += __shfl_down_sync(0xffffffffu, acc, o);

    if (lane == 0) g_s[node] = acc;
}

// ---------------------------------------------------------------------------
// K3: per-node finalize: dinv, p, and out = self-loop msg + folded bias
// ---------------------------------------------------------------------------
__global__ void node_finalize(float* __restrict__ out) {
    int n = blockIdx.x * blockDim.x + threadIdx.x;
    if (n < N_NODES) {
        float d = rsqrtf(g_deg[n]);       // deg >= 1 always (self loop)
        float s = g_s[n];
        g_dinv[n] = d;
        g_p[n]    = s * d;
        out[n]    = g_c + s * d * d;
    }
}

// ---------------------------------------------------------------------------
// K4: edge scatter, 2 edges/thread: out[dst] += p[src] * dinv[dst].
// Vectorized index loads; all 4 gathers issued before any atomic (MLP 2x R3).
// ---------------------------------------------------------------------------
__global__ void edge_scatter(const int* __restrict__ ebuf,
                             float* __restrict__ out) {
    int e = (blockIdx.x * 256 + threadIdx.x) * 2;
    if (e >= N_EDGES) return;   // N_EDGES even: no partial pairs

    int s0, s1, d0, d1;
    if (g_is64) {
        // two int64 edges = one 16B load per half; take low words
        int4 vs = ((const int4*)ebuf)[e >> 1];
        int4 vd = ((const int4*)ebuf)[((long long)N_EDGES + e) >> 1];
        s0 = vs.x; s1 = vs.z; d0 = vd.x; d1 = vd.z;
    } else {
        int2 vs = ((const int2*)ebuf)[e >> 1];
        int2 vd = ((const int2*)ebuf)[((long long)N_EDGES + e) >> 1];
        s0 = vs.x; s1 = vs.y; d0 = vd.x; d1 = vd.y;
    }

    bool v0 = (unsigned)s0 < N_NODES && (unsigned)d0 < N_NODES;
    bool v1 = (unsigned)s1 < N_NODES && (unsigned)d1 < N_NODES;

    float p0 = v0 ? g_p[s0] : 0.f;
    float p1 = v1 ? g_p[s1] : 0.f;
    float q0 = v0 ? g_dinv[d0] : 0.f;
    float q1 = v1 ? g_dinv[d1] : 0.f;

    if (v0) atomicAdd(&out[d0], p0 * q0);
    if (v1) atomicAdd(&out[d1], p1 * q1);
}

extern "C" void kernel_launch(void* const* d_in, const int* in_sizes, int n_in,
                              void* d_out, int out_size) {
    const float* state = (const float*)d_in[0];  // [N, 100, 1] f32
    const int*   ebuf  = (const int*)  d_in[1];  // [2, 200000] int32/int64 layout
    const float* W1    = (const float*)d_in[2];  // [100, 1024]
    const float* b1    = (const float*)d_in[3];  // [1024]
    const float* Wh    = (const float*)d_in[4];  // [1024, 1]
    const float* bh    = (const float*)d_in[5];  // [1]
    float* out = (float*)d_out;                  // [N, 1]

    setup_kernel      <<<1 + (F_IN + 1) + NB_DEG, 256>>>(ebuf, W1, b1, Wh, bh);
    dot_and_deg_kernel<<<NB_EDGE + NB_NODE, 256>>>(state, ebuf);
    node_finalize     <<<NB_DEG, 256>>>(out);
    edge_scatter      <<<NB_E2, 256>>>(ebuf, out);
}